// round 6
// baseline (speedup 1.0000x reference)
#include <cuda_runtime.h>
#include <cuda_bf16.h>
#include <cstdint>

// Shapes: x[256,100,512] f32, W1[1024,512] f32, b1[1024], W2[8,1024], b2[8]
// out[256,8] f32.
#define T_STEPS 100
#define B_SZ    256
#define IN_F    512
#define HID     1024
#define CLS     8
#define M_TOTAL (B_SZ * T_STEPS)   // 25600
#define KW      1536               // 3 bf16 terms x 512

// ---------------- device scratch (static; no allocations) -----------------
__device__ float         g_cur[(size_t)M_TOTAL * HID];   // 104.9 MB
__device__ __nv_bfloat16 g_A2[(size_t)M_TOTAL * KW];     // [m][a0|a1|a2] 78.6 MB
__device__ __nv_bfloat16 g_B2[(size_t)HID * KW];         // [n][b0|b1|b2]  3.1 MB

// ---------------- base-PTX helpers (sm_80+; NO 'a'-target instructions) ----
__device__ __forceinline__ uint32_t smem_u32(const void* p) {
    uint32_t a;
    asm("{ .reg .u64 t; cvta.to.shared.u64 t, %1; cvt.u32.u64 %0, t; }" : "=r"(a) : "l"(p));
    return a;
}
__device__ __forceinline__ void cp16(uint32_t dst, const void* src) {
    asm volatile("cp.async.cg.shared.global [%0], [%1], 16;" :: "r"(dst), "l"(src));
}
#define CP_COMMIT() asm volatile("cp.async.commit_group;")
#define CP_WAIT(n)  asm volatile("cp.async.wait_group %0;" :: "n"(n))

__device__ __forceinline__ void ldm_x4(uint32_t* r, uint32_t addr) {
    asm volatile("ldmatrix.sync.aligned.m8n8.x4.shared.b16 {%0,%1,%2,%3}, [%4];"
        : "=r"(r[0]), "=r"(r[1]), "=r"(r[2]), "=r"(r[3]) : "r"(addr));
}
// Isolated k=16 dot: D = A*B + 0 (the +0 is exact). NO accumulator chaining
// through the tensor core -- its chained add path rounds toward zero and the
// bias (~n_chain * 2^-25 * |acc|) is what failed rounds 4/5.
__device__ __forceinline__ void mma16816_zero(float* d, const uint32_t* a,
                                              uint32_t b0, uint32_t b1) {
    asm volatile("mma.sync.aligned.m16n8k16.row.col.f32.bf16.bf16.f32 "
        "{%0,%1,%2,%3}, {%4,%5,%6,%7}, {%8,%9}, {%10,%10,%10,%10};"
        : "=f"(d[0]), "=f"(d[1]), "=f"(d[2]), "=f"(d[3])
        : "r"(a[0]), "r"(a[1]), "r"(a[2]), "r"(a[3]), "r"(b0), "r"(b1),
          "f"(0.0f));
}

// ---------------- Kernel A: fp32 -> 3-way bf16 split ----------------------
__device__ __forceinline__ void split3_store(__nv_bfloat16* base, size_t row,
                                             int col, const float* vv) {
    __align__(8) __nv_bfloat16 t0[4], t1[4], t2[4];
    #pragma unroll
    for (int j = 0; j < 4; j++) {
        const float a = vv[j];
        t0[j] = __float2bfloat16_rn(a);
        const float r1 = a - __bfloat162float(t0[j]);
        t1[j] = __float2bfloat16_rn(r1);
        t2[j] = __float2bfloat16_rn(r1 - __bfloat162float(t1[j]));
    }
    *reinterpret_cast<uint2*>(&base[row * KW + col])        = *reinterpret_cast<uint2*>(t0);
    *reinterpret_cast<uint2*>(&base[row * KW + 512 + col])  = *reinterpret_cast<uint2*>(t1);
    *reinterpret_cast<uint2*>(&base[row * KW + 1024 + col]) = *reinterpret_cast<uint2*>(t2);
}
__global__ void convert_x(const float* __restrict__ x) {
    size_t i = (size_t)blockIdx.x * blockDim.x + threadIdx.x;   // one float4
    float4 v = reinterpret_cast<const float4*>(x)[i];
    size_t f = i * 4;
    float vv[4] = {v.x, v.y, v.z, v.w};
    split3_store(g_A2, f >> 9, (int)(f & 511), vv);
}
__global__ void convert_w(const float* __restrict__ w) {
    size_t i = (size_t)blockIdx.x * blockDim.x + threadIdx.x;
    float4 v = reinterpret_cast<const float4*>(w)[i];
    size_t f = i * 4;
    float vv[4] = {v.x, v.y, v.z, v.w};
    split3_store(g_B2, f >> 9, (int)(f & 511), vv);
}

// ---------------- GEMM helpers --------------------------------------------
// 6 product segments (8 K-chunks of 64 each): column offsets into [t0|t1|t2].
__constant__ int2 SEG_COLS[6] = {
    {0, 0},       // a0*b0
    {0, 512},     // a0*b1
    {512, 0},     // a1*b0
    {0, 1024},    // a0*b2
    {512, 512},   // a1*b1
    {1024, 0},    // a2*b0
};
#define NCHUNKS 48

__device__ __forceinline__ void load_chunk(int c, uint32_t sAst, uint32_t sBst,
                                           int tid, int mbase, int nbase) {
    const int2 sc = SEG_COLS[c >> 3];
    const int kk = (c & 7) * 64;
    const int a_col = sc.x + kk;
    const int b_col = sc.y + kk;
    #pragma unroll
    for (int p = 0; p < 4; p++) {            // A: 1024 x 16B ops (128 rows x 128B)
        const int o   = tid + p * 256;
        const int row = o >> 3;
        const int q   = o & 7;
        const uint32_t dst = sAst + row * 128 + ((q * 16) ^ ((row & 7) << 4));
        cp16(dst, &g_A2[(size_t)(mbase + row) * KW + a_col + q * 8]);
    }
    #pragma unroll
    for (int p = 0; p < 8; p++) {            // B: 2048 x 16B ops (256 rows x 128B)
        const int o   = tid + p * 256;
        const int row = o >> 3;
        const int q   = o & 7;
        const uint32_t dst = sBst + row * 128 + ((q * 16) ^ ((row & 7) << 4));
        cp16(dst, &g_B2[(size_t)(nbase + row) * KW + b_col + q * 8]);
    }
    CP_COMMIT();
}

// ---------------- Kernel B: mma.sync bf16 GEMM, software accumulation ------
// C[m][n] = sum over 6 bf16-product segments of A'[m] . B'[n]  + b1[n].
// CTA tile 128(m) x 256(n); 8 warps 2x4; warp tile 64x64; double-buffered.
// Every mma is an isolated k=16 dot (C=0); accumulation is fp32 FADD (RN).
#define SMEM_BYTES 98304

__global__ __launch_bounds__(256, 1)
void gemm_fc1_mma(const float* __restrict__ b1) {
    extern __shared__ char smem[];
    const uint32_t sb = smem_u32(smem);
    const int tid  = threadIdx.x;
    const int lane = tid & 31;
    const int wid  = tid >> 5;
    const int wm   = wid >> 2;         // 0..1  (m)
    const int wn   = wid & 3;          // 0..3  (n)
    const int mbase = blockIdx.y * 128;
    const int nbase = blockIdx.x * 256;

    const uint32_t sA[2] = {sb, sb + 16384};
    const uint32_t sB[2] = {sb + 32768, sb + 65536};

    float acc[4][8][4];
    #pragma unroll
    for (int i = 0; i < 4; i++)
        #pragma unroll
        for (int j = 0; j < 8; j++)
            #pragma unroll
            for (int k = 0; k < 4; k++) acc[i][j][k] = 0.0f;

    const int lrow  = lane & 15;           // row within 16-row ldmatrix block
    const int lhalf = (lane >> 4) * 16;    // 0 or 16 bytes (k half)

    load_chunk(0, sA[0], sB[0], tid, mbase, nbase);

    for (int c = 0; c < NCHUNKS; c++) {
        const int st = c & 1;
        if (c < NCHUNKS - 1) {
            load_chunk(c + 1, sA[st ^ 1], sB[st ^ 1], tid, mbase, nbase);
            CP_WAIT(1);
        } else {
            CP_WAIT(0);
        }
        __syncthreads();

        #pragma unroll
        for (int ks = 0; ks < 4; ks++) {
            const int cb = ks * 32 + lhalf;            // column byte before swizzle
            uint32_t a[4][4], b[4][4];
            #pragma unroll
            for (int mm = 0; mm < 4; mm++) {
                const int row = wm * 64 + mm * 16 + lrow;
                ldm_x4(a[mm], sA[st] + row * 128 + (cb ^ ((row & 7) << 4)));
            }
            #pragma unroll
            for (int bq = 0; bq < 4; bq++) {
                const int row = wn * 64 + bq * 16 + lrow;
                ldm_x4(b[bq], sB[st] + row * 128 + (cb ^ ((row & 7) << 4)));
            }
            #pragma unroll
            for (int mm = 0; mm < 4; mm++)
                #pragma unroll
                for (int bq = 0; bq < 4; bq++) {
                    float t0[4], t1[4];
                    mma16816_zero(t0, a[mm], b[bq][0], b[bq][2]);
                    mma16816_zero(t1, a[mm], b[bq][1], b[bq][3]);
                    #pragma unroll
                    for (int e = 0; e < 4; e++) {
                        acc[mm][bq * 2][e]     += t0[e];
                        acc[mm][bq * 2 + 1][e] += t1[e];
                    }
                }
        }
        __syncthreads();
    }

    // Epilogue: bias + store f32 to g_cur.
    const int qrow = lane >> 2;            // 0..7
    const int qcol = (lane & 3) * 2;       // 0,2,4,6
    #pragma unroll
    for (int bqn = 0; bqn < 8; bqn++) {
        const int n = nbase + wn * 64 + bqn * 8 + qcol;
        const float bv0 = b1[n], bv1 = b1[n + 1];
        #pragma unroll
        for (int mm = 0; mm < 4; mm++) {
            const int r0 = mbase + wm * 64 + mm * 16 + qrow;
            float2 v0 = make_float2(acc[mm][bqn][0] + bv0, acc[mm][bqn][1] + bv1);
            float2 v1 = make_float2(acc[mm][bqn][2] + bv0, acc[mm][bqn][3] + bv1);
            *reinterpret_cast<float2*>(&g_cur[(size_t)r0 * 1024 + n])       = v0;
            *reinterpret_cast<float2*>(&g_cur[(size_t)(r0 + 8) * 1024 + n]) = v1;
        }
    }
}

// ---------------- Kernel C: LIF scan + fused output GEMM ------------------
__global__ __launch_bounds__(1024, 1)
void lif_reduce(const float* __restrict__ W2, const float* __restrict__ b2,
                float* __restrict__ out) {
    const int b = blockIdx.x;
    const int h = threadIdx.x;
    const float* p = g_cur + (size_t)b * T_STEPS * HID + h;

    float mem = 0.0f, spk_sum = 0.0f;
    #pragma unroll 4
    for (int t = 0; t < T_STEPS; t++) {
        const float c = p[t * HID];
        const float reset = (mem > 1.0f) ? 1.0f : 0.0f;
        mem = 0.9f * mem + c - reset;
        spk_sum += (mem > 1.0f) ? 1.0f : 0.0f;
    }
    float part[8];
    #pragma unroll
    for (int c = 0; c < 8; c++) part[c] = spk_sum * W2[c * HID + h];
    #pragma unroll
    for (int c = 0; c < 8; c++)
        #pragma unroll
        for (int o = 16; o > 0; o >>= 1)
            part[c] += __shfl_down_sync(0xffffffffu, part[c], o);

    __shared__ float s_red[8][32];
    const int lane = h & 31, warp = h >> 5;
    if (lane == 0)
        #pragma unroll
        for (int c = 0; c < 8; c++) s_red[c][warp] = part[c];
    __syncthreads();
    if (threadIdx.x < 256) {
        const int c = threadIdx.x >> 5, w = threadIdx.x & 31;
        float v = s_red[c][w];
        #pragma unroll
        for (int o = 16; o > 0; o >>= 1)
            v += __shfl_down_sync(0xffffffffu, v, o);
        if (w == 0) out[b * CLS + c] = v + 100.0f * b2[c];
    }
}

// ---------------------------------------------------------------------------
extern "C" void kernel_launch(void* const* d_in, const int* in_sizes, int n_in,
                              void* d_out, int out_size) {
    const float* x  = (const float*)d_in[0];
    const float* W1 = (const float*)d_in[1];
    const float* b1 = (const float*)d_in[2];
    const float* W2 = (const float*)d_in[3];
    const float* b2 = (const float*)d_in[4];
    float* out = (float*)d_out;

    cudaFuncSetAttribute(gemm_fc1_mma, cudaFuncAttributeMaxDynamicSharedMemorySize,
                         SMEM_BYTES);

    convert_x<<<(M_TOTAL * IN_F / 4) / 256, 256>>>(x);   // 12800 blocks
    convert_w<<<(HID * IN_F / 4) / 256, 256>>>(W1);      // 512 blocks
    // grid: x = n-blocks (4) fastest -> CTAs sharing an A chunk launch together
    gemm_fc1_mma<<<dim3(HID / 256, M_TOTAL / 128), 256, SMEM_BYTES>>>(b1);
    lif_reduce<<<B_SZ, 1024>>>(W2, b2, out);
}